// round 9
// baseline (speedup 1.0000x reference)
#include <cuda_runtime.h>
#include <cstdint>

#define SEQ   512
#define BATCH 512
#define IDIM  300
#define HDIM  300
#define NP    320            // padded hidden for XP layout
#define JH    152            // per-CTA j-half in scan (2*152 = 304 >= 300)
#define MTOT  (SEQ*BATCH)

// GEMM tiling: 64x160 tile, 256 threads, 4m x 10n per thread (40 acc regs -> occ 3)
#define BM 64
#define BN 160
#define BK 20
#define GTH 256

// scan config: 304 threads = 76 j-pairs x 4 k-quarters; 8 batch per thread
#define STHREADS 304
#define KQ       4
#define KCH      (IDIM/KQ)        // 75
#define HB       (304*8)          // one h buffer: [304 j][8 b] floats

// -------- scratch (static device global; no allocations) --------
__device__ float g_XP[(long long)MTOT * NP];     // ~335 MB

// -------- f32x2 helpers (Blackwell packed fp32, PTX-only) --------
__device__ __forceinline__ unsigned long long bcast2(float v) {
    unsigned long long r;
    asm("mov.b64 %0, {%1, %1};" : "=l"(r) : "f"(v));
    return r;
}
__device__ __forceinline__ void ffma2(unsigned long long& d, unsigned long long a, unsigned long long b) {
    asm("fma.rn.f32x2 %0, %1, %2, %3;" : "=l"(d) : "l"(a), "l"(b), "l"(d));
}
__device__ __forceinline__ void fadd2(unsigned long long& d, unsigned long long a) {
    asm("add.rn.f32x2 %0, %1, %2;" : "=l"(d) : "l"(d), "l"(a));
}
__device__ __forceinline__ void unpack2(unsigned long long v, float& lo, float& hi) {
    asm("mov.b64 {%0, %1}, %2;" : "=f"(lo), "=f"(hi) : "l"(v));
}
__device__ __forceinline__ uint32_t smem_u32(const void* p) {
    uint32_t a;
    asm("{ .reg .u64 t; cvta.to.shared.u64 t, %1; cvt.u32.u64 %0, t; }" : "=r"(a) : "l"(p));
    return a;
}
// fast tanh: 1 - 2/(exp(2x)+1); saturates correctly at +-inf
__device__ __forceinline__ float fast_tanh(float x) {
    float e = __expf(2.0f * x);
    return 1.0f - __fdividef(2.0f, e + 1.0f);
}

// -------- x_proj GEMM: XP[m][j] = IN[m][:] . W_ih[j][:] + b_ih[j] + b_hh[j] --------
// 64x160 tile, 256 threads, thread tile 4m x 10n, occupancy 3.
// W_ih is transposed on the fly during the Bs smem fill (no prep kernel).
__global__ __launch_bounds__(GTH, 3) void gemm_xproj(const float* __restrict__ IN,
                                                     const float* __restrict__ Wih,
                                                     const float* __restrict__ bih,
                                                     const float* __restrict__ bhh) {
    __shared__ float As[BK][BM + 4];  // [k][m], padded
    __shared__ float Bs[BK][BN];      // [k][n], n contiguous
    int tid = threadIdx.x;
    int m0 = blockIdx.y * BM;
    int n0 = blockIdx.x * BN;
    int mth = tid >> 4, nth = tid & 15;   // 16 x 16
    int tm0 = mth * 4, tn0 = nth * 10;

    unsigned long long acc[4][5];
    #pragma unroll
    for (int i = 0; i < 4; i++)
        #pragma unroll
        for (int u = 0; u < 5; u++) acc[i][u] = 0ull;

    for (int kk = 0; kk < IDIM; kk += BK) {
        // As: 64x20, transposed store [k][m]
        #pragma unroll
        for (int l = 0; l < (BM * BK) / GTH; l++) {
            int idx = tid + l * GTH;
            int m = idx / BK, k = idx % BK;
            As[k][m] = IN[(long long)(m0 + m) * IDIM + kk + k];
        }
        // Bs[k][n] = Wih[n0+n][kk+k]: float4 along k, 4 STS (conflict-free: n varies per lane)
        #pragma unroll
        for (int slot = tid; slot < BN * (BK / 4); slot += GTH) {
            int n = slot % BN, kg = slot / BN;
            int gn = n0 + n;
            float4 v = make_float4(0.f, 0.f, 0.f, 0.f);
            if (gn < HDIM)
                v = *(const float4*)&Wih[(long long)gn * IDIM + kk + kg * 4];
            Bs[kg * 4 + 0][n] = v.x;
            Bs[kg * 4 + 1][n] = v.y;
            Bs[kg * 4 + 2][n] = v.z;
            Bs[kg * 4 + 3][n] = v.w;
        }
        __syncthreads();
        #pragma unroll
        for (int k = 0; k < BK; k++) {
            float4 av = *(const float4*)&As[k][tm0];
            const unsigned long long* Bk = (const unsigned long long*)&Bs[k][tn0];
            unsigned long long b0 = Bk[0], b1 = Bk[1], b2 = Bk[2], b3 = Bk[3], b4 = Bk[4];
            unsigned long long a0 = bcast2(av.x), a1 = bcast2(av.y);
            unsigned long long a2 = bcast2(av.z), a3 = bcast2(av.w);
            ffma2(acc[0][0], a0, b0); ffma2(acc[0][1], a0, b1); ffma2(acc[0][2], a0, b2);
            ffma2(acc[0][3], a0, b3); ffma2(acc[0][4], a0, b4);
            ffma2(acc[1][0], a1, b0); ffma2(acc[1][1], a1, b1); ffma2(acc[1][2], a1, b2);
            ffma2(acc[1][3], a1, b3); ffma2(acc[1][4], a1, b4);
            ffma2(acc[2][0], a2, b0); ffma2(acc[2][1], a2, b1); ffma2(acc[2][2], a2, b2);
            ffma2(acc[2][3], a2, b3); ffma2(acc[2][4], a2, b4);
            ffma2(acc[3][0], a3, b0); ffma2(acc[3][1], a3, b1); ffma2(acc[3][2], a3, b2);
            ffma2(acc[3][3], a3, b3); ffma2(acc[3][4], a3, b4);
        }
        __syncthreads();
    }
    float bias[10];
    #pragma unroll
    for (int u = 0; u < 10; u++) {
        int gn = n0 + tn0 + u;
        bias[u] = (gn < HDIM) ? (bih[gn] + bhh[gn]) : 0.f;
    }
    #pragma unroll
    for (int i = 0; i < 4; i++) {
        long long row = (long long)(m0 + tm0 + i) * NP + n0 + tn0;
        #pragma unroll
        for (int u = 0; u < 5; u++) {
            float lo, hi; unpack2(acc[i][u], lo, hi);
            float2 v = make_float2(lo + bias[2 * u], hi + bias[2 * u + 1]);
            *(float2*)&g_XP[row + 2 * u] = v;
        }
    }
}

// -------- recurrent scan: 64 clusters x 2 CTAs, 8 batch per cluster --------
// W_hh lives in REGISTERS: thread (jp, kq) holds w rows j0,j0+1 for its 75-k
// quarter (150 floats, compile-time indexed via full unroll). Per k: 2x LDS.128
// (h, warp-broadcast) + 2 bcast + 8 FFMA2 -> pure FMA-bound (~2850 cyc floor).
// Partials via smem ([slot][tid], conflict-free); each thread finishes 4
// outputs (fast_tanh), writes h local + to peer via DSMEM. Per-step sync is an
// mbarrier handshake (1 release-arrive to peer after __syncthreads; local
// acquire try_wait) instead of a full ~490-cyc cluster barrier.
__global__ __cluster_dims__(2, 1, 1) __launch_bounds__(STHREADS, 1)
void scan_kernel(const float* __restrict__ Whh, float* __restrict__ out) {
    __shared__ alignas(16) float H[2 * HB];                       // 19456 B
    __shared__ alignas(16) unsigned long long PART[8 * STHREADS]; // 19456 B
    __shared__ unsigned long long mbar;

    int tid = threadIdx.x;
    unsigned rank;
    asm("mov.u32 %0, %%cluster_ctarank;" : "=r"(rank));
    int cid = blockIdx.x >> 1;
    unsigned peer = rank ^ 1u;

    if (tid == 0) {
        asm volatile("mbarrier.init.shared.b64 [%0], 1;"
                     :: "r"(smem_u32(&mbar)) : "memory");
    }
    for (int i = tid; i < 2 * HB; i += STHREADS) H[i] = 0.f;

    // compute-role indices + W_hh into registers
    int kq = tid / 76, jp = tid % 76;
    int j0 = jp * 2;
    int jglob = rank * JH + j0;
    int kstart = kq * KCH;
    float wa[KCH], wb[KCH];
    {
        const float* ra = Whh + (long long)jglob * HDIM + kstart;
        const float* rb = ra + HDIM;
        bool va = (jglob < HDIM), vb = (jglob + 1 < HDIM);
        #pragma unroll
        for (int kk = 0; kk < KCH; kk++) {
            wa[kk] = va ? ra[kk] : 0.f;
            wb[kk] = vb ? rb[kk] : 0.f;
        }
    }

    // reduce-role indices: output row jo (local), b-quad half
    int jo = tid >> 1, half = tid & 1;
    int jglob_o = rank * JH + jo;
    int hoff = jglob_o * 8 + half * 4;               // within an H buffer
    uint32_t hbase32 = smem_u32(H);
    uint32_t mbar32 = smem_u32(&mbar);
    const float* xpbase = g_XP + (long long)(cid * 8 + half * 4) * NP + jglob_o;

    __syncthreads();
    // both CTAs' mbar + H init visible cluster-wide before any arrive/DSMEM
    asm volatile("barrier.cluster.arrive.aligned;" ::: "memory");
    asm volatile("barrier.cluster.wait.aligned;" ::: "memory");

    int p = 0;
    for (int t = 0; t < SEQ; t++) {
        // prefetch xp for this step's 4 outputs (latency hidden under MAC loop)
        const float* xr = xpbase + (long long)t * BATCH * NP;
        float x0 = xr[0];
        float x1 = xr[NP];
        float x2 = xr[2 * NP];
        float x3 = xr[3 * NP];

        // MAC over this thread's k-quarter; W in registers, h broadcast from smem
        unsigned long long A00 = 0, A01 = 0, A02 = 0, A03 = 0;
        unsigned long long A10 = 0, A11 = 0, A12 = 0, A13 = 0;
        const float* hp = H + p * HB + kstart * 8;
        #pragma unroll
        for (int kk = 0; kk < KCH; kk++) {
            ulonglong2 hA = *(const ulonglong2*)(hp + kk * 8);
            ulonglong2 hB = *(const ulonglong2*)(hp + kk * 8 + 4);
            unsigned long long w0 = bcast2(wa[kk]);
            unsigned long long w1 = bcast2(wb[kk]);
            ffma2(A00, w0, hA.x); ffma2(A01, w0, hA.y);
            ffma2(A02, w0, hB.x); ffma2(A03, w0, hB.y);
            ffma2(A10, w1, hA.x); ffma2(A11, w1, hA.y);
            ffma2(A12, w1, hB.x); ffma2(A13, w1, hB.y);
        }
        PART[0 * STHREADS + tid] = A00;
        PART[1 * STHREADS + tid] = A01;
        PART[2 * STHREADS + tid] = A02;
        PART[3 * STHREADS + tid] = A03;
        PART[4 * STHREADS + tid] = A10;
        PART[5 * STHREADS + tid] = A11;
        PART[6 * STHREADS + tid] = A12;
        PART[7 * STHREADS + tid] = A13;
        __syncthreads();

        // reduce 4 k-quarters for outputs (jo, b half*4 .. half*4+3)
        int jps = jo >> 1;                 // source j-pair
        int r = jo & 1;                    // row within pair
        int s0 = r * 4 + half * 2;         // slot of b-pair (b0,b1) of this half
        unsigned long long acc0 = PART[s0 * STHREADS + jps];
        unsigned long long acc1 = PART[(s0 + 1) * STHREADS + jps];
        #pragma unroll
        for (int q = 1; q < KQ; q++) {
            int src = q * 76 + jps;
            fadd2(acc0, PART[s0 * STHREADS + src]);
            fadd2(acc1, PART[(s0 + 1) * STHREADS + src]);
        }
        float v0, v1, v2, v3;
        unpack2(acc0, v0, v1);
        unpack2(acc1, v2, v3);
        float4 hv = make_float4(fast_tanh(x0 + v0), fast_tanh(x1 + v1),
                                fast_tanh(x2 + v2), fast_tanh(x3 + v3));
        int off = (1 - p) * HB + hoff;
        *(float4*)(H + off) = hv;
        uint32_t ra = hbase32 + off * 4;
        asm volatile("{ .reg .b32 pa; .reg .b64 d; mov.b64 d, {%2,%3}; "
                     "mapa.shared::cluster.u32 pa, %0, %1; st.shared::cluster.b64 [pa], d; }"
                     :: "r"(ra), "r"(peer), "f"(hv.x), "f"(hv.y) : "memory");
        asm volatile("{ .reg .b32 pa; .reg .b64 d; mov.b64 d, {%2,%3}; "
                     "mapa.shared::cluster.u32 pa, %0, %1; st.shared::cluster.b64 [pa], d; }"
                     :: "r"(ra + 8u), "r"(peer), "f"(hv.z), "f"(hv.w) : "memory");

        __syncthreads();   // local H writes + all threads' DSMEM stores ordered
        if (tid == 0) {
            // one release-arrive on the PEER's mbarrier (publishes our h-half)
            asm volatile("{ .reg .b32 pa; mapa.shared::cluster.u32 pa, %0, %1; "
                         "mbarrier.arrive.release.cluster.shared::cluster.b64 _, [pa]; }"
                         :: "r"(mbar32), "r"(peer) : "memory");
        }
        // wait for peer's h-half (phase parity = t&1)
        {
            unsigned ph = (unsigned)(t & 1);
            uint32_t done;
            asm volatile("{ .reg .pred p; "
                         "mbarrier.try_wait.parity.acquire.cluster.shared::cta.b64 p, [%1], %2; "
                         "selp.b32 %0, 1, 0, p; }"
                         : "=r"(done) : "r"(mbar32), "r"(ph) : "memory");
            if (!done) {
                asm volatile("{ .reg .pred P1; "
                             "WL%=: mbarrier.try_wait.parity.acquire.cluster.shared::cta.b64 P1, [%0], %1, 0x989680; "
                             "@P1 bra.uni WD%=; bra.uni WL%=; WD%=: }"
                             :: "r"(mbar32), "r"(ph) : "memory");
            }
        }
        p ^= 1;
    }

    // write final h: each CTA writes its j-half for the cluster's 8 batches
    const float* Hf = H + p * HB;
    int cb0 = cid * 8;
    for (int idx = tid; idx < 8 * JH; idx += STHREADS) {
        int b = idx / JH, jj = idx % JH;
        int j = rank * JH + jj;
        if (j < HDIM) out[(long long)(cb0 + b) * HDIM + j] = Hf[j * 8 + b];
    }
    asm volatile("barrier.cluster.arrive.aligned;" ::: "memory");
    asm volatile("barrier.cluster.wait.aligned;" ::: "memory");
}

extern "C" void kernel_launch(void* const* d_in, const int* in_sizes, int n_in,
                              void* d_out, int out_size) {
    const float* IN  = (const float*)d_in[0];
    const float* Wih = (const float*)d_in[1];
    const float* Whh = (const float*)d_in[2];
    const float* bih = (const float*)d_in[3];
    const float* bhh = (const float*)d_in[4];
    float* out = (float*)d_out;

    dim3 g(NP / BN, MTOT / BM);   // (2, 4096)
    gemm_xproj<<<g, GTH>>>(IN, Wih, bih, bhh);

    scan_kernel<<<128, STHREADS>>>(Whh, out);
}